// round 16
// baseline (speedup 1.0000x reference)
#include <cuda_runtime.h>
#include <cuda_bf16.h>
#include <cuda_fp16.h>
#include <stdint.h>

#define NB 1024
#define NP 16
#define NH 256
#define GN 25
#define GC 24
#define SG_TILES 10
#define BGC 256
#define BG_TILES 5

__device__ __nv_bfloat16 g_W1b[6][256][256];  // [net][n][k] transposed bf16
__device__ __nv_bfloat16 g_W2b[6][16][256];   // [net][n][k] bf16
__device__ __nv_bfloat16 g_h0[6][640][256];   // precomputed first-layer activations
__device__ float  g_SfP[2][4][640][12];       // partial GEMM2 sums per N-partition
__device__ float  g_BgP[2][2][320][4];        // partial bias-net sums
__device__ __half g_Gh[625 * 48];             // symmetrized, layer-packed table
__device__ float  g_Bgrid[2][320][4];         // finalized bias tables

__device__ __forceinline__ float tanh_f32(float x) {
    float y; asm("tanh.approx.f32 %0, %1;" : "=f"(y) : "f"(x)); return y;
}
__device__ __forceinline__ uint32_t pack_bf16x2(float lo, float hi) {
    uint32_t r; asm("cvt.rn.bf16x2.f32 %0, %1, %2;" : "=r"(r) : "f"(hi), "f"(lo));
    return r;
}
__device__ __forceinline__ uint32_t tanh_bf16x2(uint32_t w) {
    asm("tanh.approx.bf16x2 %0, %0;" : "+r"(w)); return w;
}
__device__ __forceinline__ void ldsm4(uint32_t r[4], uint32_t addr) {
    asm volatile("ldmatrix.sync.aligned.m8n8.x4.shared.b16 {%0,%1,%2,%3}, [%4];"
        : "=r"(r[0]), "=r"(r[1]), "=r"(r[2]), "=r"(r[3]) : "r"(addr));
}
__device__ __forceinline__ void mma16816(float c[4],
    uint32_t a0, uint32_t a1, uint32_t a2, uint32_t a3,
    uint32_t b0, uint32_t b1) {
    asm volatile(
        "mma.sync.aligned.m16n8k16.row.col.f32.bf16.bf16.f32 "
        "{%0,%1,%2,%3},{%4,%5,%6,%7},{%8,%9},{%0,%1,%2,%3};"
        : "+f"(c[0]), "+f"(c[1]), "+f"(c[2]), "+f"(c[3])
        : "r"(a0), "r"(a1), "r"(a2), "r"(a3), "r"(b0), "r"(b1));
}

// -------------------- prep: W1 transpose-convert + W2 + h0 grid ------------
__global__ void __launch_bounds__(256) prep_kernel(
    const float* __restrict__ sW0, const float* __restrict__ sb0,
    const float* __restrict__ sW1, const float* __restrict__ sW2,
    const float* __restrict__ qW0, const float* __restrict__ qb0,
    const float* __restrict__ qW1, const float* __restrict__ qW2,
    const float* __restrict__ kW0, const float* __restrict__ kb0,
    const float* __restrict__ kW1, const float* __restrict__ kW2)
{
    const int t = threadIdx.x;
    const int x = blockIdx.x, y = blockIdx.y, z = blockIdx.z;
    const int sgrid_mode = (y < 4);

    const float *W0g, *b0g, *w1src, *w2src;
    if (y < 4) { W0g = sW0 + y * 512; b0g = sb0 + y * 256;
                 w1src = sW1 + y * 65536; w2src = sW2 + y * 2304; }
    else if (y == 4) { W0g = qW0; b0g = qb0; w1src = qW1; w2src = qW2; }
    else { W0g = kW0; b0g = kb0; w1src = kW1; w2src = kW2; }

    if (z == 0) {
        if (!sgrid_mode && x >= BG_TILES) return;
        const int k0 = (t & 63) * 4;
        float w0a[4], w0b[4], c0[4];
        #pragma unroll
        for (int c = 0; c < 4; c++) {
            w0a[c] = __ldg(&W0g[k0 + c]);
            w0b[c] = sgrid_mode ? __ldg(&W0g[NH + k0 + c]) : 0.f;
            c0[c]  = __ldg(&b0g[k0 + c]);
        }
        #pragma unroll 4
        for (int rr = 0; rr < 16; rr++) {
            int row = x * 64 + rr * 4 + (t >> 6);
            float xj, xi;
            if (sgrid_mode) {
                int gA = row / GN;
                xj = (float)gA * (1.f / (float)GC);
                xi = (float)(row - gA * GN) * (1.f / (float)GC);
            } else { xj = (float)row * (1.f / (float)BGC); xi = 0.f; }
            uint2 wv;
            float a0 = fmaf(xj, w0a[0], fmaf(xi, w0b[0], c0[0]));
            float a1 = fmaf(xj, w0a[1], fmaf(xi, w0b[1], c0[1]));
            float a2 = fmaf(xj, w0a[2], fmaf(xi, w0b[2], c0[2]));
            float a3 = fmaf(xj, w0a[3], fmaf(xi, w0b[3], c0[3]));
            wv.x = tanh_bf16x2(pack_bf16x2(a0, a1));
            wv.y = tanh_bf16x2(pack_bf16x2(a2, a3));
            *reinterpret_cast<uint2*>(&g_h0[y][row][k0]) = wv;
        }
    } else {
        if (x < 4) {
            __shared__ __nv_bfloat16 tw[64][258];
            #pragma unroll 8
            for (int kk = 0; kk < 64; kk++)
                tw[kk][t] = __float2bfloat16(w1src[(x * 64 + kk) * 256 + t]);
            __syncthreads();
            const int n = t;
            #pragma unroll
            for (int j = 0; j < 8; j++) {
                __align__(16) __nv_bfloat16 tmp[8];
                #pragma unroll
                for (int d = 0; d < 8; d++) tmp[d] = tw[8 * j + d][n];
                *reinterpret_cast<uint4*>(&g_W1b[y][n][x * 64 + 8 * j]) =
                    *reinterpret_cast<const uint4*>(tmp);
            }
        } else if (x == 4) {
            const int nv = sgrid_mode ? 9 : 3;
            #pragma unroll
            for (int n = 0; n < 16; n++) {
                float v = (n < nv) ? __ldg(&w2src[t * nv + n]) : 0.f;
                g_W2b[y][n][t] = __float2bfloat16(v);
            }
        }
    }
}

// -------------------- MLP grid-evaluation (copies + GEMM only) -------------
struct __align__(16) SmemLayout {
    __nv_bfloat16 W1t[128][264];
    __nv_bfloat16 h0[64][264];
    __nv_bfloat16 W2t[16][264];
    float red[8][32][16];
    float b1s[128];
};

__global__ void __launch_bounds__(256, 1) mlp_grid(
    const float* __restrict__ sb1, const float* __restrict__ qb1,
    const float* __restrict__ kb1)
{
    extern __shared__ char smem_raw[];
    SmemLayout& S = *reinterpret_cast<SmemLayout*>(smem_raw);
    const int t = threadIdx.x;
    const int warp = t >> 5, lane = t & 31;
    const int g = lane >> 2, tg = lane & 3;
    const int mw = warp & 1, nw = warp >> 1;
    const int y = blockIdx.y;
    const int ns = blockIdx.z;
    const int sgrid_mode = (y < 4);
    const int ntiles = sgrid_mode ? SG_TILES : BG_TILES;
    if ((int)blockIdx.x >= ntiles) return;
    const int out_valid = sgrid_mode ? 9 : 3;

    const float* b1g;
    if (y < 4) b1g = sb1 + y * 256;
    else if (y == 4) b1g = qb1;
    else b1g = kb1;

    const int tile = blockIdx.x;
    const int row0 = tile * 64;

    {
        const __nv_bfloat16* w1p = &g_W1b[y][ns * 128][0];
        #pragma unroll
        for (int i = 0; i < 16; i++) {
            int idx = t + i * 256;
            int n = idx >> 5, kc = idx & 31;
            *reinterpret_cast<uint4*>(&S.W1t[n][kc * 8]) =
                *reinterpret_cast<const uint4*>(&w1p[n * 256 + kc * 8]);
        }
        const __nv_bfloat16* h0p = &g_h0[y][row0][0];
        #pragma unroll
        for (int i = 0; i < 8; i++) {
            int idx = t + i * 256;
            int r = idx >> 5, kc = idx & 31;
            *reinterpret_cast<uint4*>(&S.h0[r][kc * 8]) =
                *reinterpret_cast<const uint4*>(&h0p[r * 256 + kc * 8]);
        }
        {
            int n = t >> 4, kc = t & 15;
            *reinterpret_cast<uint4*>(&S.W2t[n][kc * 8]) =
                *reinterpret_cast<const uint4*>(&g_W2b[y][n][ns * 128 + kc * 8]);
        }
        if (t < 128) S.b1s[t] = b1g[ns * 128 + t];
    }
    __syncthreads();

    const int a_r = (lane & 7) + ((lane & 8) ? 8 : 0);
    const int a_c = (lane & 16) ? 8 : 0;
    const uint32_t h0base = (uint32_t)__cvta_generic_to_shared(&S.h0[0][0]);

    float acc[2][4][4];
    #pragma unroll
    for (int mt = 0; mt < 2; mt++)
        #pragma unroll
        for (int nt = 0; nt < 4; nt++)
            #pragma unroll
            for (int c = 0; c < 4; c++) acc[mt][nt][c] = 0.f;

    const int rbase = mw * 32;
    #pragma unroll 4
    for (int kt = 0; kt < 16; kt++) {
        uint32_t a[2][4];
        #pragma unroll
        for (int mt = 0; mt < 2; mt++) {
            uint32_t addr = h0base +
                (uint32_t)(((rbase + mt * 16 + a_r) * 264 + kt * 16 + a_c) * 2);
            ldsm4(a[mt], addr);
        }
        #pragma unroll
        for (int nt = 0; nt < 4; nt++) {
            int n = nw * 32 + nt * 8 + g;
            uint32_t b0 = *reinterpret_cast<const uint32_t*>(&S.W1t[n][kt * 16 + 2 * tg]);
            uint32_t b1 = *reinterpret_cast<const uint32_t*>(&S.W1t[n][kt * 16 + 2 * tg + 8]);
            mma16816(acc[0][nt], a[0][0], a[0][1], a[0][2], a[0][3], b0, b1);
            mma16816(acc[1][nt], a[1][0], a[1][1], a[1][2], a[1][3], b0, b1);
        }
    }

    uint32_t A2[2][4][2];
    #pragma unroll
    for (int nt = 0; nt < 4; nt++) {
        int c0 = nw * 32 + nt * 8 + 2 * tg;
        float bb0 = S.b1s[c0], bb1 = S.b1s[c0 + 1];
        #pragma unroll
        for (int mt = 0; mt < 2; mt++) {
            A2[mt][nt][0] = tanh_bf16x2(
                pack_bf16x2(acc[mt][nt][0] + bb0, acc[mt][nt][1] + bb1));
            A2[mt][nt][1] = tanh_bf16x2(
                pack_bf16x2(acc[mt][nt][2] + bb0, acc[mt][nt][3] + bb1));
        }
    }

    float c2[2][2][4];
    #pragma unroll
    for (int mt = 0; mt < 2; mt++)
        #pragma unroll
        for (int nb = 0; nb < 2; nb++)
            #pragma unroll
            for (int c = 0; c < 4; c++) c2[mt][nb][c] = 0.f;

    #pragma unroll
    for (int kt2 = 0; kt2 < 2; kt2++) {
        #pragma unroll
        for (int mt = 0; mt < 2; mt++) {
            uint32_t a0 = A2[mt][2 * kt2][0],     a1 = A2[mt][2 * kt2][1];
            uint32_t a2 = A2[mt][2 * kt2 + 1][0], a3 = A2[mt][2 * kt2 + 1][1];
            #pragma unroll
            for (int nb = 0; nb < 2; nb++) {
                uint32_t b0 = *reinterpret_cast<const uint32_t*>(
                    &S.W2t[nb * 8 + g][nw * 32 + kt2 * 16 + 2 * tg]);
                uint32_t b1 = *reinterpret_cast<const uint32_t*>(
                    &S.W2t[nb * 8 + g][nw * 32 + kt2 * 16 + 2 * tg + 8]);
                mma16816(c2[mt][nb], a0, a1, a2, a3, b0, b1);
            }
        }
    }

    #pragma unroll
    for (int mt = 0; mt < 2; mt++)
        #pragma unroll
        for (int nb = 0; nb < 2; nb++)
            #pragma unroll
            for (int c = 0; c < 4; c++) {
                int rr = mt * 16 + g + ((c >> 1) & 1) * 8;
                int cc = nb * 8 + 2 * tg + (c & 1);
                S.red[warp][rr][cc] = c2[mt][nb][c];
            }
    __syncthreads();

    {
        int r64 = t >> 2, cq = t & 3;
        int mw2 = r64 >> 5, r32 = r64 & 31;
        #pragma unroll
        for (int cc = 0; cc < 4; cc++) {
            int col = cq * 4 + cc;
            float s = 0.f;
            #pragma unroll
            for (int nn = 0; nn < 4; nn++) s += S.red[nn * 2 + mw2][r32][col];
            if (col < out_valid) {
                int row = row0 + r64;
                if (sgrid_mode) g_SfP[ns][y][row][col] = s;
                else            g_BgP[ns][y - 4][row][col] = s;
            }
        }
    }
}

// -------------------- finalize: combine partitions, +b2, tanh, symmetrize --
__global__ void __launch_bounds__(256) sym_kernel(
    const float* __restrict__ sb2, const float* __restrict__ qb2,
    const float* __restrict__ kb2)
{
    int idx = blockIdx.x * 256 + threadIdx.x;
    if (idx < 625 * 4) {
        int node = idx >> 2, l = idx & 3;
        int u = node / GN, v = node - u * GN;
        int na = u * GN + v, nb = v * GN + u;
        const float* b2 = sb2 + l * 9;
        __half* dst = g_Gh + (size_t)node * 48 + l * 12;
        #pragma unroll
        for (int a = 0; a < 3; a++)
            #pragma unroll
            for (int c = 0; c < 3; c++) {
                float fa = tanh_f32(g_SfP[0][l][na][a*3+c] + g_SfP[1][l][na][a*3+c] + b2[a*3+c]);
                float fb = tanh_f32(g_SfP[0][l][nb][c*3+a] + g_SfP[1][l][nb][c*3+a] + b2[c*3+a]);
                dst[a * 3 + c] = __float2half(fa + fb);
            }
        dst[9] = dst[10] = dst[11] = __float2half(0.f);
    } else {
        int k = idx - 2500;
        if (k < 640) {
            int net = k >= 320, node = k - net * 320;
            const float* b2 = net ? kb2 : qb2;
            #pragma unroll
            for (int e = 0; e < 3; e++)
                g_Bgrid[net][node][e] =
                    tanh_f32(g_BgP[0][net][node][e] + g_BgP[1][net][node][e] + b2[e]);
        }
    }
}

// -------------------- assemble: cooperative coalesced gather ----------------
// Pair P (i<=j): 4 corners at nodes {n00, n00+1} and {n00+GN, n00+GN+1} —
// two contiguous 192B regions. All 256 threads stream 136*24 uint4 into smem
// with consecutive addresses per region (sector-coalesced), then the 136
// upper threads combine from smem and publish to blob; lower threads read
// the transpose (G(v,u) = G(u,v)^T).
struct __align__(16) AsmSmem {
    uint4 raw[136 * 24];          // 52224 B
    __half blob[256][50];         // 25600 B
    float qf[48], pf[48];
    float fr[16];  int cl[16];
    float frB[16]; int clB[16];
    int   n00s[136];
    float w4s[136][4];
};

__global__ void __launch_bounds__(256) assemble_interp(
    const float* __restrict__ q, const float* __restrict__ p,
    const float* __restrict__ m, const float* __restrict__ dtp,
    float* __restrict__ out)
{
    extern __shared__ char asm_raw[];
    AsmSmem& S = *reinterpret_cast<AsmSmem*>(asm_raw);
    const int b = blockIdx.x, t = threadIdx.x;
    if (t < 48) { S.qf[t] = q[b * 48 + t]; S.pf[t] = p[b * 48 + t]; }
    if (t < 16) {
        float mv = m[b * 16 + t];
        float u = mv * (float)GC; int c = (int)u; if (c > GC - 1) c = GC - 1;
        S.cl[t] = c; S.fr[t] = u - (float)c;
        float uB = mv * (float)BGC; int cB = (int)uB; if (cB > BGC - 1) cB = BGC - 1;
        S.clB[t] = cB; S.frB[t] = uB - (float)cB;
    }
    float dt = dtp[0];
    const float scale = dt * dt * dt;
    __syncthreads();

    const int i = t >> 4, j = t & 15;
    const bool upper = (i <= j);
    const int P = upper ? (i * 16 + j - ((i * (i + 1)) >> 1)) : -1;

    // ---- pair metadata ----
    if (upper) {
        const int cu = S.cl[j], cv = S.cl[i];
        const float fu = S.fr[j], fv = S.fr[i];
        S.n00s[P] = cu * GN + cv;
        S.w4s[P][0] = (1.f - fu) * (1.f - fv);
        S.w4s[P][1] = (1.f - fu) * fv;
        S.w4s[P][2] = fu * (1.f - fv);
        S.w4s[P][3] = fu * fv;
    }
    __syncthreads();

    // ---- cooperative coalesced gather: 136 pairs x 24 uint4 ----
    const uint4* Gp = reinterpret_cast<const uint4*>(g_Gh);
    for (int idx = t; idx < 136 * 24; idx += 256) {
        int pp = idx / 24, sub = idx - pp * 24;
        int reg = sub >= 12;                 // region 0 / 1
        int word = sub - reg * 12;           // 0..11 within 192B region
        int node = S.n00s[pp] + reg * GN;    // region start node
        S.raw[idx] = __ldg(&Gp[node * 6 + word]);
    }
    __syncthreads();

    // ---- upper threads combine corners -> blob ----
    if (upper) {
        __half2 Ah[24];
        #pragma unroll
        for (int k = 0; k < 24; k++) Ah[k] = __float2half2_rn(0.f);
        const uint4* rp = &S.raw[P * 24];
        #pragma unroll
        for (int c = 0; c < 4; c++) {
            const __half2* h = reinterpret_cast<const __half2*>(rp + c * 6);
            const __half2 w2 = __float2half2_rn(S.w4s[P][c]);
            #pragma unroll
            for (int k = 0; k < 24; k++) Ah[k] = __hfma2(w2, h[k], Ah[k]);
        }
        #pragma unroll
        for (int k = 0; k < 24; k++)
            *reinterpret_cast<__half2*>(&S.blob[t][2 * k]) = Ah[k];
    }
    __syncthreads();

    // ---- fetch (transpose for lower) ----
    const int src = upper ? t : (j * 16 + i);
    float Af[4][9];
    #pragma unroll
    for (int l = 0; l < 4; l++)
        #pragma unroll
        for (int x = 0; x < 9; x++) {
            const int xt = (x % 3) * 3 + (x / 3);
            Af[l][x] = __half2float(S.blob[src][l * 12 + (upper ? x : xt)]);
        }

    #pragma unroll
    for (int l = 0; l < 4; l++) {
        const float* sv = (l & 1) ? S.pf : S.qf;
        float*       dv = (l & 1) ? S.qf : S.pf;
        float sj0 = sv[j * 3 + 0], sj1 = sv[j * 3 + 1], sj2 = sv[j * 3 + 2];
        float y0 = Af[l][0] * sj0 + Af[l][1] * sj1 + Af[l][2] * sj2;
        float y1 = Af[l][3] * sj0 + Af[l][4] * sj1 + Af[l][5] * sj2;
        float y2 = Af[l][6] * sj0 + Af[l][7] * sj1 + Af[l][8] * sj2;
        #pragma unroll
        for (int off = 8; off; off >>= 1) {
            y0 += __shfl_xor_sync(0xffffffffu, y0, off);
            y1 += __shfl_xor_sync(0xffffffffu, y1, off);
            y2 += __shfl_xor_sync(0xffffffffu, y2, off);
        }
        if (j == 0) {
            dv[i * 3 + 0] += scale * y0;
            dv[i * 3 + 1] += scale * y1;
            dv[i * 3 + 2] += scale * y2;
        }
        __syncthreads();
    }

    if (t < 48) {
        int pi = t / 3, e = t - pi * 3;
        int c = S.clB[pi]; float f = S.frB[pi];
        float bq0 = g_Bgrid[0][c][e], bq1 = g_Bgrid[0][c + 1][e];
        float bp0 = g_Bgrid[1][c][e], bp1 = g_Bgrid[1][c + 1][e];
        out[b * 48 + t]           = S.qf[t] + (bq0 + f * (bq1 - bq0)) * scale;
        out[NB * 48 + b * 48 + t] = S.pf[t] + (bp0 + f * (bp1 - bp0)) * scale;
    }
}

// -------------------- launch ------------------------------------------------
extern "C" void kernel_launch(void* const* d_in, const int* in_sizes, int n_in,
                              void* d_out, int out_size) {
    const float* q   = (const float*)d_in[0];
    const float* p   = (const float*)d_in[1];
    const float* m   = (const float*)d_in[2];
    const float* dt  = (const float*)d_in[3];
    const float* sW0 = (const float*)d_in[4];
    const float* sb0 = (const float*)d_in[5];
    const float* sW1 = (const float*)d_in[6];
    const float* sb1 = (const float*)d_in[7];
    const float* sW2 = (const float*)d_in[8];
    const float* sb2 = (const float*)d_in[9];
    const float* qW0 = (const float*)d_in[10];
    const float* qb0 = (const float*)d_in[11];
    const float* qW1 = (const float*)d_in[12];
    const float* qb1 = (const float*)d_in[13];
    const float* qW2 = (const float*)d_in[14];
    const float* qb2 = (const float*)d_in[15];
    const float* kW0 = (const float*)d_in[16];
    const float* kb0 = (const float*)d_in[17];
    const float* kW1 = (const float*)d_in[18];
    const float* kb1 = (const float*)d_in[19];
    const float* kW2 = (const float*)d_in[20];
    const float* kb2 = (const float*)d_in[21];
    float* out = (float*)d_out;

    static bool once = false;
    if (!once) {
        cudaFuncSetAttribute(mlp_grid, cudaFuncAttributeMaxDynamicSharedMemorySize,
                             (int)sizeof(SmemLayout));
        cudaFuncSetAttribute(assemble_interp, cudaFuncAttributeMaxDynamicSharedMemorySize,
                             (int)sizeof(AsmSmem));
        once = true;
    }
    {
        dim3 grid(SG_TILES, 6, 2);
        prep_kernel<<<grid, 256>>>(
            sW0, sb0, sW1, sW2, qW0, qb0, qW1, qW2, kW0, kb0, kW1, kW2);
    }
    {
        dim3 grid(SG_TILES, 6, 2);
        mlp_grid<<<grid, 256, sizeof(SmemLayout)>>>(sb1, qb1, kb1);
    }
    sym_kernel<<<13, 256>>>(sb2, qb2, kb2);
    assemble_interp<<<NB, 256, sizeof(AsmSmem)>>>(q, p, m, dt, out);
}

// round 17
// speedup vs baseline: 1.7025x; 1.7025x over previous
#include <cuda_runtime.h>
#include <cuda_bf16.h>
#include <cuda_fp16.h>
#include <stdint.h>

#define NB 1024
#define NP 16
#define NH 256
#define GN 25
#define GC 24
#define SG_TILES 10
#define BGC 256
#define BG_TILES 5

__device__ __nv_bfloat16 g_W1b[6][256][256];  // [net][n][k] transposed bf16
__device__ __nv_bfloat16 g_W2b[6][16][256];   // [net][n][k] bf16
__device__ __nv_bfloat16 g_h0[6][640][256];   // precomputed first-layer activations
__device__ float  g_SfP[2][4][640][12];       // partial GEMM2 sums per N-partition
__device__ float  g_BgP[2][2][320][4];        // partial bias-net sums
__device__ uint8_t g_G8[625 * 48];            // symmetrized table, fp8 e4m3 (48B/node)
__device__ float  g_Bgrid[2][320][4];         // finalized bias tables

__device__ __forceinline__ float tanh_f32(float x) {
    float y; asm("tanh.approx.f32 %0, %1;" : "=f"(y) : "f"(x)); return y;
}
__device__ __forceinline__ uint32_t pack_bf16x2(float lo, float hi) {
    uint32_t r; asm("cvt.rn.bf16x2.f32 %0, %1, %2;" : "=r"(r) : "f"(hi), "f"(lo));
    return r;
}
__device__ __forceinline__ uint32_t tanh_bf16x2(uint32_t w) {
    asm("tanh.approx.bf16x2 %0, %0;" : "+r"(w)); return w;
}
__device__ __forceinline__ uint16_t pack_e4m3x2(float lo, float hi) {
    uint16_t r;
    asm("cvt.rn.satfinite.e4m3x2.f32 %0, %1, %2;" : "=h"(r) : "f"(hi), "f"(lo));
    return r;
}
__device__ __forceinline__ uint32_t e4m3x2_to_h2(uint16_t v) {
    uint32_t r;
    asm("cvt.rn.f16x2.e4m3x2 %0, %1;" : "=r"(r) : "h"(v));
    return r;
}
__device__ __forceinline__ void ldsm4(uint32_t r[4], uint32_t addr) {
    asm volatile("ldmatrix.sync.aligned.m8n8.x4.shared.b16 {%0,%1,%2,%3}, [%4];"
        : "=r"(r[0]), "=r"(r[1]), "=r"(r[2]), "=r"(r[3]) : "r"(addr));
}
__device__ __forceinline__ void mma16816(float c[4],
    uint32_t a0, uint32_t a1, uint32_t a2, uint32_t a3,
    uint32_t b0, uint32_t b1) {
    asm volatile(
        "mma.sync.aligned.m16n8k16.row.col.f32.bf16.bf16.f32 "
        "{%0,%1,%2,%3},{%4,%5,%6,%7},{%8,%9},{%0,%1,%2,%3};"
        : "+f"(c[0]), "+f"(c[1]), "+f"(c[2]), "+f"(c[3])
        : "r"(a0), "r"(a1), "r"(a2), "r"(a3), "r"(b0), "r"(b1));
}

// -------------------- prep: W1 transpose-convert + W2 + h0 grid ------------
__global__ void __launch_bounds__(256) prep_kernel(
    const float* __restrict__ sW0, const float* __restrict__ sb0,
    const float* __restrict__ sW1, const float* __restrict__ sW2,
    const float* __restrict__ qW0, const float* __restrict__ qb0,
    const float* __restrict__ qW1, const float* __restrict__ qW2,
    const float* __restrict__ kW0, const float* __restrict__ kb0,
    const float* __restrict__ kW1, const float* __restrict__ kW2)
{
    const int t = threadIdx.x;
    const int x = blockIdx.x, y = blockIdx.y, z = blockIdx.z;
    const int sgrid_mode = (y < 4);

    const float *W0g, *b0g, *w1src, *w2src;
    if (y < 4) { W0g = sW0 + y * 512; b0g = sb0 + y * 256;
                 w1src = sW1 + y * 65536; w2src = sW2 + y * 2304; }
    else if (y == 4) { W0g = qW0; b0g = qb0; w1src = qW1; w2src = qW2; }
    else { W0g = kW0; b0g = kb0; w1src = kW1; w2src = kW2; }

    if (z == 0) {
        if (!sgrid_mode && x >= BG_TILES) return;
        const int k0 = (t & 63) * 4;
        float w0a[4], w0b[4], c0[4];
        #pragma unroll
        for (int c = 0; c < 4; c++) {
            w0a[c] = __ldg(&W0g[k0 + c]);
            w0b[c] = sgrid_mode ? __ldg(&W0g[NH + k0 + c]) : 0.f;
            c0[c]  = __ldg(&b0g[k0 + c]);
        }
        #pragma unroll 4
        for (int rr = 0; rr < 16; rr++) {
            int row = x * 64 + rr * 4 + (t >> 6);
            float xj, xi;
            if (sgrid_mode) {
                int gA = row / GN;
                xj = (float)gA * (1.f / (float)GC);
                xi = (float)(row - gA * GN) * (1.f / (float)GC);
            } else { xj = (float)row * (1.f / (float)BGC); xi = 0.f; }
            uint2 wv;
            float a0 = fmaf(xj, w0a[0], fmaf(xi, w0b[0], c0[0]));
            float a1 = fmaf(xj, w0a[1], fmaf(xi, w0b[1], c0[1]));
            float a2 = fmaf(xj, w0a[2], fmaf(xi, w0b[2], c0[2]));
            float a3 = fmaf(xj, w0a[3], fmaf(xi, w0b[3], c0[3]));
            wv.x = tanh_bf16x2(pack_bf16x2(a0, a1));
            wv.y = tanh_bf16x2(pack_bf16x2(a2, a3));
            *reinterpret_cast<uint2*>(&g_h0[y][row][k0]) = wv;
        }
    } else {
        if (x < 4) {
            __shared__ __nv_bfloat16 tw[64][258];
            #pragma unroll 8
            for (int kk = 0; kk < 64; kk++)
                tw[kk][t] = __float2bfloat16(w1src[(x * 64 + kk) * 256 + t]);
            __syncthreads();
            const int n = t;
            #pragma unroll
            for (int j = 0; j < 8; j++) {
                __align__(16) __nv_bfloat16 tmp[8];
                #pragma unroll
                for (int d = 0; d < 8; d++) tmp[d] = tw[8 * j + d][n];
                *reinterpret_cast<uint4*>(&g_W1b[y][n][x * 64 + 8 * j]) =
                    *reinterpret_cast<const uint4*>(tmp);
            }
        } else if (x == 4) {
            const int nv = sgrid_mode ? 9 : 3;
            #pragma unroll
            for (int n = 0; n < 16; n++) {
                float v = (n < nv) ? __ldg(&w2src[t * nv + n]) : 0.f;
                g_W2b[y][n][t] = __float2bfloat16(v);
            }
        }
    }
}

// -------------------- MLP grid-evaluation (copies + GEMM only) -------------
struct __align__(16) SmemLayout {
    __nv_bfloat16 W1t[128][264];
    __nv_bfloat16 h0[64][264];
    __nv_bfloat16 W2t[16][264];
    float red[8][32][16];
    float b1s[128];
};

__global__ void __launch_bounds__(256, 1) mlp_grid(
    const float* __restrict__ sb1, const float* __restrict__ qb1,
    const float* __restrict__ kb1)
{
    extern __shared__ char smem_raw[];
    SmemLayout& S = *reinterpret_cast<SmemLayout*>(smem_raw);
    const int t = threadIdx.x;
    const int warp = t >> 5, lane = t & 31;
    const int g = lane >> 2, tg = lane & 3;
    const int mw = warp & 1, nw = warp >> 1;
    const int y = blockIdx.y;
    const int ns = blockIdx.z;
    const int sgrid_mode = (y < 4);
    const int ntiles = sgrid_mode ? SG_TILES : BG_TILES;
    if ((int)blockIdx.x >= ntiles) return;
    const int out_valid = sgrid_mode ? 9 : 3;

    const float* b1g;
    if (y < 4) b1g = sb1 + y * 256;
    else if (y == 4) b1g = qb1;
    else b1g = kb1;

    const int tile = blockIdx.x;
    const int row0 = tile * 64;

    {
        const __nv_bfloat16* w1p = &g_W1b[y][ns * 128][0];
        #pragma unroll
        for (int i = 0; i < 16; i++) {
            int idx = t + i * 256;
            int n = idx >> 5, kc = idx & 31;
            *reinterpret_cast<uint4*>(&S.W1t[n][kc * 8]) =
                *reinterpret_cast<const uint4*>(&w1p[n * 256 + kc * 8]);
        }
        const __nv_bfloat16* h0p = &g_h0[y][row0][0];
        #pragma unroll
        for (int i = 0; i < 8; i++) {
            int idx = t + i * 256;
            int r = idx >> 5, kc = idx & 31;
            *reinterpret_cast<uint4*>(&S.h0[r][kc * 8]) =
                *reinterpret_cast<const uint4*>(&h0p[r * 256 + kc * 8]);
        }
        {
            int n = t >> 4, kc = t & 15;
            *reinterpret_cast<uint4*>(&S.W2t[n][kc * 8]) =
                *reinterpret_cast<const uint4*>(&g_W2b[y][n][ns * 128 + kc * 8]);
        }
        if (t < 128) S.b1s[t] = b1g[ns * 128 + t];
    }
    __syncthreads();

    const int a_r = (lane & 7) + ((lane & 8) ? 8 : 0);
    const int a_c = (lane & 16) ? 8 : 0;
    const uint32_t h0base = (uint32_t)__cvta_generic_to_shared(&S.h0[0][0]);

    float acc[2][4][4];
    #pragma unroll
    for (int mt = 0; mt < 2; mt++)
        #pragma unroll
        for (int nt = 0; nt < 4; nt++)
            #pragma unroll
            for (int c = 0; c < 4; c++) acc[mt][nt][c] = 0.f;

    const int rbase = mw * 32;
    #pragma unroll 4
    for (int kt = 0; kt < 16; kt++) {
        uint32_t a[2][4];
        #pragma unroll
        for (int mt = 0; mt < 2; mt++) {
            uint32_t addr = h0base +
                (uint32_t)(((rbase + mt * 16 + a_r) * 264 + kt * 16 + a_c) * 2);
            ldsm4(a[mt], addr);
        }
        #pragma unroll
        for (int nt = 0; nt < 4; nt++) {
            int n = nw * 32 + nt * 8 + g;
            uint32_t b0 = *reinterpret_cast<const uint32_t*>(&S.W1t[n][kt * 16 + 2 * tg]);
            uint32_t b1 = *reinterpret_cast<const uint32_t*>(&S.W1t[n][kt * 16 + 2 * tg + 8]);
            mma16816(acc[0][nt], a[0][0], a[0][1], a[0][2], a[0][3], b0, b1);
            mma16816(acc[1][nt], a[1][0], a[1][1], a[1][2], a[1][3], b0, b1);
        }
    }

    uint32_t A2[2][4][2];
    #pragma unroll
    for (int nt = 0; nt < 4; nt++) {
        int c0 = nw * 32 + nt * 8 + 2 * tg;
        float bb0 = S.b1s[c0], bb1 = S.b1s[c0 + 1];
        #pragma unroll
        for (int mt = 0; mt < 2; mt++) {
            A2[mt][nt][0] = tanh_bf16x2(
                pack_bf16x2(acc[mt][nt][0] + bb0, acc[mt][nt][1] + bb1));
            A2[mt][nt][1] = tanh_bf16x2(
                pack_bf16x2(acc[mt][nt][2] + bb0, acc[mt][nt][3] + bb1));
        }
    }

    float c2[2][2][4];
    #pragma unroll
    for (int mt = 0; mt < 2; mt++)
        #pragma unroll
        for (int nb = 0; nb < 2; nb++)
            #pragma unroll
            for (int c = 0; c < 4; c++) c2[mt][nb][c] = 0.f;

    #pragma unroll
    for (int kt2 = 0; kt2 < 2; kt2++) {
        #pragma unroll
        for (int mt = 0; mt < 2; mt++) {
            uint32_t a0 = A2[mt][2 * kt2][0],     a1 = A2[mt][2 * kt2][1];
            uint32_t a2 = A2[mt][2 * kt2 + 1][0], a3 = A2[mt][2 * kt2 + 1][1];
            #pragma unroll
            for (int nb = 0; nb < 2; nb++) {
                uint32_t b0 = *reinterpret_cast<const uint32_t*>(
                    &S.W2t[nb * 8 + g][nw * 32 + kt2 * 16 + 2 * tg]);
                uint32_t b1 = *reinterpret_cast<const uint32_t*>(
                    &S.W2t[nb * 8 + g][nw * 32 + kt2 * 16 + 2 * tg + 8]);
                mma16816(c2[mt][nb], a0, a1, a2, a3, b0, b1);
            }
        }
    }

    #pragma unroll
    for (int mt = 0; mt < 2; mt++)
        #pragma unroll
        for (int nb = 0; nb < 2; nb++)
            #pragma unroll
            for (int c = 0; c < 4; c++) {
                int rr = mt * 16 + g + ((c >> 1) & 1) * 8;
                int cc = nb * 8 + 2 * tg + (c & 1);
                S.red[warp][rr][cc] = c2[mt][nb][c];
            }
    __syncthreads();

    {
        int r64 = t >> 2, cq = t & 3;
        int mw2 = r64 >> 5, r32 = r64 & 31;
        #pragma unroll
        for (int cc = 0; cc < 4; cc++) {
            int col = cq * 4 + cc;
            float s = 0.f;
            #pragma unroll
            for (int nn = 0; nn < 4; nn++) s += S.red[nn * 2 + mw2][r32][col];
            if (col < out_valid) {
                int row = row0 + r64;
                if (sgrid_mode) g_SfP[ns][y][row][col] = s;
                else            g_BgP[ns][y - 4][row][col] = s;
            }
        }
    }
}

// -------------------- finalize: combine, +b2, tanh, symmetrize -> fp8 ------
__global__ void __launch_bounds__(256) sym_kernel(
    const float* __restrict__ sb2, const float* __restrict__ qb2,
    const float* __restrict__ kb2)
{
    int idx = blockIdx.x * 256 + threadIdx.x;
    if (idx < 625 * 4) {
        int node = idx >> 2, l = idx & 3;
        int u = node / GN, v = node - u * GN;
        int na = u * GN + v, nb = v * GN + u;
        const float* b2 = sb2 + l * 9;
        float val[12];
        #pragma unroll
        for (int a = 0; a < 3; a++)
            #pragma unroll
            for (int c = 0; c < 3; c++) {
                float fa = tanh_f32(g_SfP[0][l][na][a*3+c] + g_SfP[1][l][na][a*3+c] + b2[a*3+c]);
                float fb = tanh_f32(g_SfP[0][l][nb][c*3+a] + g_SfP[1][l][nb][c*3+a] + b2[c*3+a]);
                val[a * 3 + c] = fa + fb;
            }
        val[9] = val[10] = val[11] = 0.f;
        uint16_t* dst = reinterpret_cast<uint16_t*>(g_G8 + (size_t)node * 48 + l * 12);
        #pragma unroll
        for (int k = 0; k < 6; k++)
            dst[k] = pack_e4m3x2(val[2 * k], val[2 * k + 1]);
    } else {
        int k = idx - 2500;
        if (k < 640) {
            int net = k >= 320, node = k - net * 320;
            const float* b2 = net ? kb2 : qb2;
            #pragma unroll
            for (int e = 0; e < 3; e++)
                g_Bgrid[net][node][e] =
                    tanh_f32(g_BgP[0][net][node][e] + g_BgP[1][net][node][e] + b2[e]);
        }
    }
}

// -------------------- assemble: fp8 gather, transpose-shared ----------------
__device__ __forceinline__ void acc_corner_f8(int node, float w, __half2 A[24]) {
    const uint4* p = reinterpret_cast<const uint4*>(g_G8 + (size_t)node * 48);
    uint4 d[3];
    #pragma unroll
    for (int k = 0; k < 3; k++) d[k] = __ldg(&p[k]);
    const uint32_t* u = reinterpret_cast<const uint32_t*>(d);
    const __half2 w2 = __float2half2_rn(w);
    #pragma unroll
    for (int k = 0; k < 12; k++) {
        uint32_t v = u[k];
        uint32_t h0 = e4m3x2_to_h2((uint16_t)(v & 0xFFFFu));
        uint32_t h1 = e4m3x2_to_h2((uint16_t)(v >> 16));
        A[2 * k]     = __hfma2(w2, *reinterpret_cast<__half2*>(&h0), A[2 * k]);
        A[2 * k + 1] = __hfma2(w2, *reinterpret_cast<__half2*>(&h1), A[2 * k + 1]);
    }
}

__global__ void __launch_bounds__(256) assemble_interp(
    const float* __restrict__ q, const float* __restrict__ p,
    const float* __restrict__ m, const float* __restrict__ dtp,
    float* __restrict__ out)
{
    __shared__ float qf[48], pf[48];
    __shared__ float fr[16]; __shared__ int cl[16];
    __shared__ float frB[16]; __shared__ int clB[16];
    __shared__ __half blob[256][50];
    const int b = blockIdx.x, t = threadIdx.x;
    if (t < 48) { qf[t] = q[b * 48 + t]; pf[t] = p[b * 48 + t]; }
    if (t < 16) {
        float mv = m[b * 16 + t];
        float u = mv * (float)GC; int c = (int)u; if (c > GC - 1) c = GC - 1;
        cl[t] = c; fr[t] = u - (float)c;
        float uB = mv * (float)BGC; int cB = (int)uB; if (cB > BGC - 1) cB = BGC - 1;
        clB[t] = cB; frB[t] = uB - (float)cB;
    }
    float dt = dtp[0];
    const float scale = dt * dt * dt;
    __syncthreads();

    const int i = t >> 4, j = t & 15;
    const bool upper = (i <= j);

    if (upper) {
        const int cu = cl[j], cv = cl[i];
        const float fu = fr[j], fv = fr[i];
        const float w00 = (1.f - fu) * (1.f - fv), w01 = (1.f - fu) * fv;
        const float w10 = fu * (1.f - fv),         w11 = fu * fv;
        const int n00 = cu * GN + cv;
        __half2 Ah[24];
        #pragma unroll
        for (int k = 0; k < 24; k++) Ah[k] = __float2half2_rn(0.f);
        acc_corner_f8(n00,          w00, Ah);
        acc_corner_f8(n00 + 1,      w01, Ah);
        acc_corner_f8(n00 + GN,     w10, Ah);
        acc_corner_f8(n00 + GN + 1, w11, Ah);
        #pragma unroll
        for (int k = 0; k < 24; k++)
            *reinterpret_cast<__half2*>(&blob[t][2 * k]) = Ah[k];
    }
    __syncthreads();

    const int src = upper ? t : (j * 16 + i);
    float Af[4][9];
    #pragma unroll
    for (int l = 0; l < 4; l++)
        #pragma unroll
        for (int x = 0; x < 9; x++) {
            const int xt = (x % 3) * 3 + (x / 3);
            Af[l][x] = __half2float(blob[src][l * 12 + (upper ? x : xt)]);
        }

    #pragma unroll
    for (int l = 0; l < 4; l++) {
        const float* sv = (l & 1) ? pf : qf;
        float*       dv = (l & 1) ? qf : pf;
        float sj0 = sv[j * 3 + 0], sj1 = sv[j * 3 + 1], sj2 = sv[j * 3 + 2];
        float y0 = Af[l][0] * sj0 + Af[l][1] * sj1 + Af[l][2] * sj2;
        float y1 = Af[l][3] * sj0 + Af[l][4] * sj1 + Af[l][5] * sj2;
        float y2 = Af[l][6] * sj0 + Af[l][7] * sj1 + Af[l][8] * sj2;
        #pragma unroll
        for (int off = 8; off; off >>= 1) {
            y0 += __shfl_xor_sync(0xffffffffu, y0, off);
            y1 += __shfl_xor_sync(0xffffffffu, y1, off);
            y2 += __shfl_xor_sync(0xffffffffu, y2, off);
        }
        if (j == 0) {
            dv[i * 3 + 0] += scale * y0;
            dv[i * 3 + 1] += scale * y1;
            dv[i * 3 + 2] += scale * y2;
        }
        __syncthreads();
    }

    if (t < 48) {
        int pi = t / 3, e = t - pi * 3;
        int c = clB[pi]; float f = frB[pi];
        float bq0 = g_Bgrid[0][c][e], bq1 = g_Bgrid[0][c + 1][e];
        float bp0 = g_Bgrid[1][c][e], bp1 = g_Bgrid[1][c + 1][e];
        out[b * 48 + t]           = qf[t] + (bq0 + f * (bq1 - bq0)) * scale;
        out[NB * 48 + b * 48 + t] = pf[t] + (bp0 + f * (bp1 - bp0)) * scale;
    }
}

// -------------------- launch ------------------------------------------------
extern "C" void kernel_launch(void* const* d_in, const int* in_sizes, int n_in,
                              void* d_out, int out_size) {
    const float* q   = (const float*)d_in[0];
    const float* p   = (const float*)d_in[1];
    const float* m   = (const float*)d_in[2];
    const float* dt  = (const float*)d_in[3];
    const float* sW0 = (const float*)d_in[4];
    const float* sb0 = (const float*)d_in[5];
    const float* sW1 = (const float*)d_in[6];
    const float* sb1 = (const float*)d_in[7];
    const float* sW2 = (const float*)d_in[8];
    const float* sb2 = (const float*)d_in[9];
    const float* qW0 = (const float*)d_in[10];
    const float* qb0 = (const float*)d_in[11];
    const float* qW1 = (const float*)d_in[12];
    const float* qb1 = (const float*)d_in[13];
    const float* qW2 = (const float*)d_in[14];
    const float* qb2 = (const float*)d_in[15];
    const float* kW0 = (const float*)d_in[16];
    const float* kb0 = (const float*)d_in[17];
    const float* kW1 = (const float*)d_in[18];
    const float* kb1 = (const float*)d_in[19];
    const float* kW2 = (const float*)d_in[20];
    const float* kb2 = (const float*)d_in[21];
    float* out = (float*)d_out;

    static bool once = false;
    if (!once) {
        cudaFuncSetAttribute(mlp_grid, cudaFuncAttributeMaxDynamicSharedMemorySize,
                             (int)sizeof(SmemLayout));
        once = true;
    }
    {
        dim3 grid(SG_TILES, 6, 2);
        prep_kernel<<<grid, 256>>>(
            sW0, sb0, sW1, sW2, qW0, qb0, qW1, qW2, kW0, kb0, kW1, kW2);
    }
    {
        dim3 grid(SG_TILES, 6, 2);
        mlp_grid<<<grid, 256, sizeof(SmemLayout)>>>(sb1, qb1, kb1);
    }
    sym_kernel<<<13, 256>>>(sb2, qb2, kb2);
    assemble_interp<<<NB, 256>>>(q, p, m, dt, out);
}